// round 1
// baseline (speedup 1.0000x reference)
#include <cuda_runtime.h>
#include <math.h>
#include <stdint.h>

#define NN 50000
#define EE 800000
#define HID 128
#define NH 4
#define CH 32
#define LAY 3
#define EDIM 3
#define NEG 0.2f
#define LN_EPS 1e-5f

// ---------------- scratch (static device globals; no allocation) ----------------
__device__ float g_xl[NN * HID];
__device__ float g_xr[NN * HID];
__device__ float g_agg[NN * HID];
__device__ int   g_cnt[NN];
__device__ int   g_off[NN + 1];
__device__ int   g_cur[NN];
__device__ int   g_srcs[EE];
__device__ float g_ea[EE * 3];
__device__ float g_stats[6];

// ---------------- CSR build ----------------
__global__ void zero_kernel() {
    int i = blockIdx.x * blockDim.x + threadIdx.x;
    if (i < NN) g_cnt[i] = 0;
    if (i < 6) g_stats[i] = 0.f;
}

__global__ void hist_kernel(const int* __restrict__ ei) {
    int e = blockIdx.x * blockDim.x + threadIdx.x;
    if (e >= EE) return;
    atomicAdd(&g_cnt[ei[EE + e]], 1);
}

__global__ void scan_kernel() {
    __shared__ int sh[1024];
    __shared__ int carry_s;
    int tid = threadIdx.x;
    if (tid == 0) carry_s = 0;
    __syncthreads();
    for (int base = 0; base < NN; base += 1024) {
        int i = base + tid;
        int v = (i < NN) ? g_cnt[i] : 0;
        sh[tid] = v;
        __syncthreads();
        #pragma unroll
        for (int d = 1; d < 1024; d <<= 1) {
            int add = (tid >= d) ? sh[tid - d] : 0;
            __syncthreads();
            sh[tid] += add;
            __syncthreads();
        }
        int carry = carry_s;
        if (i < NN) g_off[i] = carry + sh[tid] - v;  // exclusive
        int total = sh[1023];
        __syncthreads();
        if (tid == 0) carry_s = carry + total;
        __syncthreads();
    }
    if (tid == 0) g_off[NN] = carry_s;
}

__global__ void copy_cur_kernel() {
    int i = blockIdx.x * blockDim.x + threadIdx.x;
    if (i < NN) g_cur[i] = g_off[i];
}

__global__ void scatter_kernel(const int* __restrict__ ei, const float* __restrict__ eattr) {
    int e = blockIdx.x * blockDim.x + threadIdx.x;
    if (e >= EE) return;
    int s = ei[e];
    int d = ei[EE + e];
    int p = atomicAdd(&g_cur[d], 1);
    g_srcs[p] = s;
    g_ea[p * 3 + 0] = eattr[e * 3 + 0];
    g_ea[p * 3 + 1] = eattr[e * 3 + 1];
    g_ea[p * 3 + 2] = eattr[e * 3 + 2];
}

// ---------------- fused GEMM: out = act(norm(A)) @ {W0, W1} ----------------
// NB=2: computes A@W0 -> O0 and A@W1 -> O1 (attention lin_l / lin_r pair)
// NB=1: computes A@W0 + bias -> O0 (final projection)
// If stats != nullptr: input is (A - mean)*rstd*lnw + lnb followed by exact GELU.
template <int NB>
__global__ __launch_bounds__(256, 1) void gemm_kernel(
    const float* __restrict__ A,
    const float* __restrict__ W0, const float* __restrict__ W1,
    float* __restrict__ O0, float* __restrict__ O1,
    const float* __restrict__ stats,
    const float* __restrict__ lnw, const float* __restrict__ lnb,
    const float* __restrict__ bias,
    int nrows, float inv_count)
{
    extern __shared__ float smem[];
    float* Ws = smem;               // NB * 128*128
    float* Hs = smem + NB * 16384;  // 64 * 128
    const int tid = threadIdx.x;

    // load weights (vectorized)
    {
        float4* d = (float4*)Ws;
        const float4* w0 = (const float4*)W0;
        #pragma unroll
        for (int i = tid; i < 4096; i += 256) d[i] = w0[i];
        if (NB == 2) {
            const float4* w1 = (const float4*)W1;
            #pragma unroll
            for (int i = tid; i < 4096; i += 256) d[4096 + i] = w1[i];
        }
    }

    float mean = 0.f, rstd = 1.f;
    if (stats) {
        float s = stats[0], q = stats[1];
        mean = s * inv_count;
        float var = q * inv_count - mean * mean;
        rstd = rsqrtf(var + LN_EPS);
    }

    const int row0 = blockIdx.x * 64;
    // load 64x128 H tile, fused layernorm(graph) + exact GELU
    for (int i = tid; i < 64 * 128; i += 256) {
        int r = i >> 7, c = i & 127;
        int gr = row0 + r;
        float v = (gr < nrows) ? A[gr * 128 + c] : 0.f;
        if (stats) {
            v = (v - mean) * rstd * lnw[c] + lnb[c];
            v = 0.5f * v * (1.f + erff(v * 0.70710678118654752f));
        }
        Hs[i] = v;
    }
    __syncthreads();

    constexpr int TN = (NB == 2) ? 8 : 4;
    const int warp = tid >> 5, lane = tid & 31;
    const int r0 = warp * 8;
    const int c0 = lane * TN;
    const float* Wbase = Ws + ((NB == 2) ? ((c0 >> 7) * 16384) : 0) + (c0 & 127);

    float acc[8][TN];
    #pragma unroll
    for (int i = 0; i < 8; i++)
        #pragma unroll
        for (int j = 0; j < TN; j++) acc[i][j] = 0.f;

    #pragma unroll 4
    for (int k = 0; k < 128; k++) {
        float a[8];
        #pragma unroll
        for (int i = 0; i < 8; i++) a[i] = Hs[(r0 + i) * 128 + k];
        float b[TN];
        {
            const float4* p = (const float4*)(Wbase + k * 128);
            float4 b0 = p[0];
            b[0] = b0.x; b[1] = b0.y; b[2] = b0.z; b[3] = b0.w;
            if (TN == 8) {
                float4 b1 = p[1];
                b[4] = b1.x; b[5] = b1.y; b[6] = b1.z; b[7] = b1.w;
            }
        }
        #pragma unroll
        for (int i = 0; i < 8; i++)
            #pragma unroll
            for (int j = 0; j < TN; j++) acc[i][j] += a[i] * b[j];
    }

    #pragma unroll
    for (int i = 0; i < 8; i++) {
        int gr = row0 + r0 + i;
        if (gr >= nrows) continue;
        float* dst;
        if (NB == 2 && c0 >= 128) dst = O1 + gr * 128 + (c0 - 128);
        else                      dst = O0 + gr * 128 + c0;
        #pragma unroll
        for (int j = 0; j < TN; j++) {
            float v = acc[i][j];
            if (NB == 1 && bias) v += bias[c0 + j];
            dst[j] = v;
        }
    }
}

// ---------------- edge aggregation: one warp per dst node, online softmax ----------------
__global__ __launch_bounds__(256) void edge_kernel(
    const float* __restrict__ We,   // [3][128] slice for this layer
    const float* __restrict__ att)  // [4][32]  slice
{
    __shared__ float We_s[3 * 128];
    __shared__ float att_s[128];
    for (int i = threadIdx.x; i < 384; i += blockDim.x) We_s[i] = We[i];
    for (int i = threadIdx.x; i < 128; i += blockDim.x) att_s[i] = att[i];
    __syncthreads();

    const int gw = (blockIdx.x * blockDim.x + threadIdx.x) >> 5;
    const int lane = threadIdx.x & 31;
    if (gw >= NN) return;
    const int node = gw;
    const int e0 = g_off[node], e1 = g_off[node + 1];

    float xrv[NH], accv[NH], mh[NH], sh_[NH];
    #pragma unroll
    for (int h = 0; h < NH; h++) {
        xrv[h] = g_xr[node * 128 + h * 32 + lane];
        accv[h] = 0.f; mh[h] = -INFINITY; sh_[h] = 0.f;
    }

    for (int base = e0; base < e1; base += 32) {
        int cnt = min(32, e1 - base);
        int s = 0; float a0 = 0.f, a1 = 0.f, a2 = 0.f;
        if (lane < cnt) {
            s = g_srcs[base + lane];
            a0 = g_ea[(base + lane) * 3 + 0];
            a1 = g_ea[(base + lane) * 3 + 1];
            a2 = g_ea[(base + lane) * 3 + 2];
        }
        for (int j = 0; j < cnt; j++) {
            int src  = __shfl_sync(0xffffffffu, s, j);
            float b0 = __shfl_sync(0xffffffffu, a0, j);
            float b1 = __shfl_sync(0xffffffffu, a1, j);
            float b2 = __shfl_sync(0xffffffffu, a2, j);

            float xlv[NH], p[NH];
            #pragma unroll
            for (int h = 0; h < NH; h++) {
                int c = h * 32 + lane;
                xlv[h] = g_xl[src * 128 + c];
                float ea = b0 * We_s[c] + b1 * We_s[128 + c] + b2 * We_s[256 + c];
                float v = xlv[h] + xrv[h] + ea;
                v = (v > 0.f) ? v : NEG * v;
                p[h] = v * att_s[c];
            }
            #pragma unroll
            for (int o = 16; o > 0; o >>= 1) {
                p[0] += __shfl_xor_sync(0xffffffffu, p[0], o);
                p[1] += __shfl_xor_sync(0xffffffffu, p[1], o);
                p[2] += __shfl_xor_sync(0xffffffffu, p[2], o);
                p[3] += __shfl_xor_sync(0xffffffffu, p[3], o);
            }
            #pragma unroll
            for (int h = 0; h < NH; h++) {
                float lg = p[h];
                float nm = fmaxf(mh[h], lg);
                float sc = __expf(mh[h] - nm);   // 0 on first edge (-inf)
                float w  = __expf(lg - nm);
                sh_[h]  = sh_[h] * sc + w;
                accv[h] = accv[h] * sc + w * xlv[h];
                mh[h] = nm;
            }
        }
    }
    #pragma unroll
    for (int h = 0; h < NH; h++)
        g_agg[node * 128 + h * 32 + lane] = accv[h] / (sh_[h] + 1e-16f);
}

// ---------------- whole-matrix mean/var reduction ----------------
__global__ void stats_kernel(const float* __restrict__ a, int n4, float* st) {
    float s = 0.f, q = 0.f;
    const float4* a4 = (const float4*)a;
    for (int i = blockIdx.x * blockDim.x + threadIdx.x; i < n4; i += gridDim.x * blockDim.x) {
        float4 v = a4[i];
        s += v.x + v.y + v.z + v.w;
        q += v.x * v.x + v.y * v.y + v.z * v.z + v.w * v.w;
    }
    #pragma unroll
    for (int o = 16; o > 0; o >>= 1) {
        s += __shfl_xor_sync(0xffffffffu, s, o);
        q += __shfl_xor_sync(0xffffffffu, q, o);
    }
    __shared__ float ss[8], qq[8];
    int w = threadIdx.x >> 5;
    if ((threadIdx.x & 31) == 0) { ss[w] = s; qq[w] = q; }
    __syncthreads();
    if (threadIdx.x == 0) {
        float S = 0.f, Q = 0.f;
        #pragma unroll
        for (int i = 0; i < 8; i++) { S += ss[i]; Q += qq[i]; }
        atomicAdd(st, S);
        atomicAdd(st + 1, Q);
    }
}

// ---------------- launch ----------------
extern "C" void kernel_launch(void* const* d_in, const int* in_sizes, int n_in,
                              void* d_out, int out_size)
{
    const float* x     = (const float*)d_in[0];
    const int*   ei    = (const int*)  d_in[1];
    const float* eattr = (const float*)d_in[2];
    const float* Wl    = (const float*)d_in[3];   // [3][128][128]
    const float* Wr    = (const float*)d_in[4];
    const float* We    = (const float*)d_in[5];   // [3][3][128]
    const float* att   = (const float*)d_in[6];   // [3][4][32]
    const float* lnw   = (const float*)d_in[7];   // [3][128]
    const float* lnb   = (const float*)d_in[8];
    const float* Wout  = (const float*)d_in[9];   // [128][128]
    const float* bout  = (const float*)d_in[10];  // [128]
    float* out = (float*)d_out;

    const size_t SMEM2 = (2 * 16384 + 64 * 128) * sizeof(float); // 160 KB
    const size_t SMEM1 = (1 * 16384 + 64 * 128) * sizeof(float); //  96 KB
    cudaFuncSetAttribute(gemm_kernel<2>, cudaFuncAttributeMaxDynamicSharedMemorySize, (int)SMEM2);
    cudaFuncSetAttribute(gemm_kernel<1>, cudaFuncAttributeMaxDynamicSharedMemorySize, (int)SMEM1);

    const float inv_count = 1.f / (float)(NN * HID);
    const int GEMM_BLOCKS = (NN + 63) / 64;   // 782
    const int EDGE_BLOCKS = (NN + 7) / 8;     // 6250 (8 warps/block)

    // CSR build (graph is identical every call; rebuilt deterministically-enough)
    zero_kernel<<<(NN + 255) / 256, 256>>>();
    hist_kernel<<<(EE + 255) / 256, 256>>>(ei);
    scan_kernel<<<1, 1024>>>();
    copy_cur_kernel<<<(NN + 255) / 256, 256>>>();
    scatter_kernel<<<(EE + 255) / 256, 256>>>(ei, eattr);

    float* xl; cudaGetSymbolAddress((void**)&xl, g_xl);
    float* xr; cudaGetSymbolAddress((void**)&xr, g_xr);
    float* agg; cudaGetSymbolAddress((void**)&agg, g_agg);
    float* st; cudaGetSymbolAddress((void**)&st, g_stats);

    for (int l = 0; l < LAY; l++) {
        const float* A = (l == 0) ? x : agg;
        const float* stats = (l == 0) ? nullptr : (st + 2 * (l - 1));
        const float* w = (l == 0) ? nullptr : (lnw + 128 * (l - 1));
        const float* b = (l == 0) ? nullptr : (lnb + 128 * (l - 1));
        gemm_kernel<2><<<GEMM_BLOCKS, 256, SMEM2>>>(
            A, Wl + l * 16384, Wr + l * 16384, xl, xr,
            stats, w, b, nullptr, NN, inv_count);
        edge_kernel<<<EDGE_BLOCKS, 256>>>(We + l * 384, att + l * 128);
        stats_kernel<<<512, 256>>>(agg, NN * HID / 4, st + 2 * l);
    }

    gemm_kernel<1><<<GEMM_BLOCKS, 256, SMEM1>>>(
        agg, Wout, nullptr, out, nullptr,
        st + 4, lnw + 256, lnb + 256, bout, NN, inv_count);
}

// round 3
// speedup vs baseline: 1.5379x; 1.5379x over previous
#include <cuda_runtime.h>
#include <math.h>
#include <stdint.h>

#define NN 50000
#define EE 800000
#define HID 128
#define NH 4
#define LAY 3
#define NEG 0.2f
#define LN_EPS 1e-5f
#define LO_OFF (7 * 16384)

// ---------------- scratch ----------------
__device__ float  g_xl[NN * HID];
__device__ float  g_xr[NN * HID];
__device__ float  g_agg[NN * HID];
__device__ int    g_cnt[NN];
__device__ int    g_off[NN + 1];
__device__ int    g_cur[NN];
__device__ float4 g_edge[EE];             // {src_bits, a0, a1, a2}
__device__ float  g_stats[6];
__device__ int    g_bsum[256];
__device__ int    g_boff[256];
__device__ uint32_t g_wpack[14 * 16384];  // hi[7 mats] then lo[7 mats], fragment order

// ---------------- helpers ----------------
__device__ __forceinline__ uint32_t f2tf32(float v) {
    uint32_t o;
    asm("cvt.rna.tf32.f32 %0, %1;" : "=r"(o) : "f"(v));
    return o;
}

__device__ __forceinline__ void mma_tf32(float c[4], const uint32_t a[4], const uint32_t b[2]) {
    asm volatile(
        "mma.sync.aligned.m16n8k8.row.col.f32.tf32.tf32.f32 "
        "{%0,%1,%2,%3}, {%4,%5,%6,%7}, {%8,%9}, {%0,%1,%2,%3};\n"
        : "+f"(c[0]), "+f"(c[1]), "+f"(c[2]), "+f"(c[3])
        : "r"(a[0]), "r"(a[1]), "r"(a[2]), "r"(a[3]), "r"(b[0]), "r"(b[1]));
}

__device__ __forceinline__ int incl_scan256(int v) {
    int lane = threadIdx.x & 31, w = threadIdx.x >> 5;
    #pragma unroll
    for (int o = 1; o < 32; o <<= 1) {
        int n = __shfl_up_sync(0xffffffffu, v, o);
        if (lane >= o) v += n;
    }
    __shared__ int ws[8];
    if (lane == 31) ws[w] = v;
    __syncthreads();
    int add = 0;
    #pragma unroll
    for (int i = 0; i < 8; i++) if (i < w) add += ws[i];
    __syncthreads();
    return v + add;
}

// ---------------- weight pack: fragment-order tf32 hi/lo ----------------
__global__ void pack_kernel(const float* __restrict__ W, uint32_t* __restrict__ P, int nmat) {
    int idx = blockIdx.x * blockDim.x + threadIdx.x;
    if (idx >= nmat * 16384) return;
    int mat = idx >> 14;
    int r = idx & 16383;
    int kt   = r >> 10;
    int nt   = (r >> 6) & 15;
    int lane = (r >> 1) & 31;
    int reg  = r & 1;
    int k = kt * 8 + (lane & 3) + reg * 4;
    int n = nt * 8 + (lane >> 2);
    float w = W[mat * 16384 + k * 128 + n];
    uint32_t hi = f2tf32(w);
    P[idx] = hi;
    P[idx + LO_OFF] = f2tf32(w - __uint_as_float(hi));
}

// ---------------- CSR build ----------------
__global__ void zero_kernel() {
    int i = blockIdx.x * blockDim.x + threadIdx.x;
    if (i < NN) g_cnt[i] = 0;
    if (i < 6) g_stats[i] = 0.f;
    if (i == 6) g_off[NN] = EE;
}

__global__ void hist_kernel(const int* __restrict__ ei) {
    int e = blockIdx.x * blockDim.x + threadIdx.x;
    if (e >= EE) return;
    atomicAdd(&g_cnt[ei[EE + e]], 1);
}

__global__ void blocksum_kernel() {
    __shared__ int sh[256];
    int i = blockIdx.x * 256 + threadIdx.x;
    sh[threadIdx.x] = (i < NN) ? g_cnt[i] : 0;
    __syncthreads();
    for (int d = 128; d > 0; d >>= 1) {
        if (threadIdx.x < d) sh[threadIdx.x] += sh[threadIdx.x + d];
        __syncthreads();
    }
    if (threadIdx.x == 0) g_bsum[blockIdx.x] = sh[0];
}

__global__ void bscan_kernel(int nblk) {
    int t = threadIdx.x;
    int v = (t < nblk) ? g_bsum[t] : 0;
    int incl = incl_scan256(v);
    if (t < nblk) g_boff[t] = incl - v;
}

__global__ void offs_kernel() {
    int i = blockIdx.x * 256 + threadIdx.x;
    int v = (i < NN) ? g_cnt[i] : 0;
    int incl = incl_scan256(v);
    int off = g_boff[blockIdx.x] + incl - v;
    if (i < NN) { g_off[i] = off; g_cur[i] = off; }
}

__global__ void scatter_kernel(const int* __restrict__ ei, const float* __restrict__ eattr) {
    int e = blockIdx.x * blockDim.x + threadIdx.x;
    if (e >= EE) return;
    int s = ei[e];
    int d = ei[EE + e];
    int p = atomicAdd(&g_cur[d], 1);
    g_edge[p] = make_float4(__int_as_float(s),
                            eattr[e * 3 + 0], eattr[e * 3 + 1], eattr[e * 3 + 2]);
}

// ---------------- 3xTF32 tensor-core GEMM: O = act(norm(A)) @ W ----------------
template <int NTW>
__global__ __launch_bounds__(256) void gemm_mma(
    const float* __restrict__ A,
    const uint32_t* __restrict__ P0, const uint32_t* __restrict__ P1,
    float* __restrict__ O0, float* __restrict__ O1,
    const float* __restrict__ stats,
    const float* __restrict__ lnw, const float* __restrict__ lnb,
    const float* __restrict__ bias,
    int nrows, float inv_count)
{
    extern __shared__ float smem[];
    float* Hs = smem;             // hi tile 64x132
    float* Ls = smem + 64 * 132;  // lo tile 64x132

    float mean = 0.f, rstd = 1.f;
    if (stats) {
        float s = stats[0], q = stats[1];
        mean = s * inv_count;
        float var = q * inv_count - mean * mean;
        rstd = rsqrtf(var + LN_EPS);
    }

    const int tid = threadIdx.x;
    const int row0 = blockIdx.x * 64;
    for (int i = tid; i < 64 * 128; i += 256) {
        int r = i >> 7, c = i & 127;
        int gr = row0 + r;
        float v = (gr < nrows) ? A[gr * 128 + c] : 0.f;
        if (stats) {
            v = (v - mean) * rstd * lnw[c] + lnb[c];
            v = 0.5f * v * (1.f + erff(v * 0.70710678118654752f));
        }
        uint32_t hi = f2tf32(v);
        Hs[r * 132 + c] = __uint_as_float(hi);
        Ls[r * 132 + c] = __uint_as_float(f2tf32(v - __uint_as_float(hi)));
    }
    __syncthreads();

    const int w = tid >> 5, lane = tid & 31;
    const int g = lane >> 2, tig = lane & 3;

    const uint32_t* P;
    int colbase;
    if (NTW == 4) { P = (w < 4) ? P0 : P1; colbase = (w & 3) * 32; }
    else          { P = P0;                colbase = w * 16; }
    const int nt0 = colbase >> 3;

    float acc[4][NTW][4];
    #pragma unroll
    for (int mt = 0; mt < 4; mt++)
        #pragma unroll
        for (int nt = 0; nt < NTW; nt++)
            #pragma unroll
            for (int j = 0; j < 4; j++) acc[mt][nt][j] = 0.f;

    const uint2* Pv = (const uint2*)P;

    for (int kt = 0; kt < 16; kt++) {
        uint32_t ah[4][4], al[4][4];
        #pragma unroll
        for (int mt = 0; mt < 4; mt++) {
            int r = mt * 16 + g;
            int col = kt * 8 + tig;
            ah[mt][0] = __float_as_uint(Hs[r * 132 + col]);
            ah[mt][1] = __float_as_uint(Hs[(r + 8) * 132 + col]);
            ah[mt][2] = __float_as_uint(Hs[r * 132 + col + 4]);
            ah[mt][3] = __float_as_uint(Hs[(r + 8) * 132 + col + 4]);
            al[mt][0] = __float_as_uint(Ls[r * 132 + col]);
            al[mt][1] = __float_as_uint(Ls[(r + 8) * 132 + col]);
            al[mt][2] = __float_as_uint(Ls[r * 132 + col + 4]);
            al[mt][3] = __float_as_uint(Ls[(r + 8) * 132 + col + 4]);
        }
        uint2 bh[NTW], bl[NTW];
        #pragma unroll
        for (int nt = 0; nt < NTW; nt++) {
            int o = (kt * 16 + nt0 + nt) * 32 + lane;
            bh[nt] = Pv[o];
            bl[nt] = Pv[o + LO_OFF / 2];
        }

        #pragma unroll
        for (int mt = 0; mt < 4; mt++)
            #pragma unroll
            for (int nt = 0; nt < NTW; nt++) {
                mma_tf32(acc[mt][nt], ah[mt], (const uint32_t*)&bh[nt]);
                mma_tf32(acc[mt][nt], ah[mt], (const uint32_t*)&bl[nt]);
                mma_tf32(acc[mt][nt], al[mt], (const uint32_t*)&bh[nt]);
            }
    }

    float* O = (NTW == 4 && w >= 4) ? O1 : O0;
    #pragma unroll
    for (int mt = 0; mt < 4; mt++) {
        int r = row0 + mt * 16 + g;
        #pragma unroll
        for (int nt = 0; nt < NTW; nt++) {
            int col = colbase + nt * 8 + tig * 2;
            float b0 = 0.f, b1 = 0.f;
            if (NTW == 2 && bias) { b0 = bias[col]; b1 = bias[col + 1]; }
            if (r < nrows) {
                O[r * 128 + col]     = acc[mt][nt][0] + b0;
                O[r * 128 + col + 1] = acc[mt][nt][1] + b1;
            }
            if (r + 8 < nrows) {
                O[(r + 8) * 128 + col]     = acc[mt][nt][2] + b0;
                O[(r + 8) * 128 + col + 1] = acc[mt][nt][3] + b1;
            }
        }
    }
}

// ---------------- edge aggregation: warp/node, 8 lanes/edge, split softmax ----------------
__global__ __launch_bounds__(256, 2) void edge_kernel(
    const float* __restrict__ We,   // [3][128]
    const float* __restrict__ att)  // [4][32]
{
    __shared__ float4 We_s[3][32];
    for (int i = threadIdx.x; i < 96; i += 256) {
        int d = i >> 5, j = i & 31;
        We_s[d][j] = ((const float4*)(We + d * 128))[j];
    }
    __syncthreads();

    const int gw = (blockIdx.x * 256 + threadIdx.x) >> 5;
    if (gw >= NN) return;
    const int lane = threadIdx.x & 31;
    const int g = lane >> 3, l = lane & 7;
    const unsigned gmask = 0xFFu << (g * 8);   // group-scoped shuffle mask

    float4 att4[NH], xr4[NH], acc[NH];
    float m[NH], s[NH];
    #pragma unroll
    for (int h = 0; h < NH; h++) {
        att4[h] = ((const float4*)att)[h * 8 + l];
        xr4[h]  = ((const float4*)(g_xr + gw * 128))[h * 8 + l];
        acc[h]  = make_float4(0.f, 0.f, 0.f, 0.f);
        m[h] = -INFINITY;
        s[h] = 0.f;
    }

    const int e0 = g_off[gw], e1 = g_off[gw + 1];

    for (int e = e0 + g; e < e1; e += 4) {
        float4 rec = g_edge[e];
        int src = __float_as_int(rec.x);
        const float4* xlp = (const float4*)(g_xl + src * 128);
        float4 xl[NH];
        #pragma unroll
        for (int h = 0; h < NH; h++) xl[h] = __ldg(xlp + h * 8 + l);

        float p[NH];
        #pragma unroll
        for (int h = 0; h < NH; h++) {
            float4 w0 = We_s[0][h * 8 + l];
            float4 w1 = We_s[1][h * 8 + l];
            float4 w2 = We_s[2][h * 8 + l];
            float ph = 0.f;
            float v;
            v = xl[h].x + xr4[h].x + rec.y * w0.x + rec.z * w1.x + rec.w * w2.x;
            v = (v > 0.f) ? v : NEG * v; ph += v * att4[h].x;
            v = xl[h].y + xr4[h].y + rec.y * w0.y + rec.z * w1.y + rec.w * w2.y;
            v = (v > 0.f) ? v : NEG * v; ph += v * att4[h].y;
            v = xl[h].z + xr4[h].z + rec.y * w0.z + rec.z * w1.z + rec.w * w2.z;
            v = (v > 0.f) ? v : NEG * v; ph += v * att4[h].z;
            v = xl[h].w + xr4[h].w + rec.y * w0.w + rec.z * w1.w + rec.w * w2.w;
            v = (v > 0.f) ? v : NEG * v; ph += v * att4[h].w;
            p[h] = ph;
        }
        // reduce logits within 8-lane group (group-scoped mask: legal under divergence)
        #pragma unroll
        for (int h = 0; h < NH; h++) {
            p[h] += __shfl_xor_sync(gmask, p[h], 1);
            p[h] += __shfl_xor_sync(gmask, p[h], 2);
            p[h] += __shfl_xor_sync(gmask, p[h], 4);
        }
        // online softmax update (per group)
        #pragma unroll
        for (int h = 0; h < NH; h++) {
            float nm = fmaxf(m[h], p[h]);
            float sc = __expf(m[h] - nm);
            float wg = __expf(p[h] - nm);
            s[h] = s[h] * sc + wg;
            acc[h].x = acc[h].x * sc + wg * xl[h].x;
            acc[h].y = acc[h].y * sc + wg * xl[h].y;
            acc[h].z = acc[h].z * sc + wg * xl[h].z;
            acc[h].w = acc[h].w * sc + wg * xl[h].w;
            m[h] = nm;
        }
    }

    // merge the 4 groups (all 32 lanes converged here)
    #pragma unroll
    for (int h = 0; h < NH; h++) {
        float mg = m[h];
        float M = fmaxf(mg, __shfl_xor_sync(0xffffffffu, mg, 8));
        M = fmaxf(M, __shfl_xor_sync(0xffffffffu, M, 16));
        float f = (mg == -INFINITY) ? 0.f : __expf(mg - M);
        float S = s[h] * f;
        S += __shfl_xor_sync(0xffffffffu, S, 8);
        S += __shfl_xor_sync(0xffffffffu, S, 16);
        float ax = acc[h].x * f, ay = acc[h].y * f, az = acc[h].z * f, aw = acc[h].w * f;
        ax += __shfl_xor_sync(0xffffffffu, ax, 8);
        ay += __shfl_xor_sync(0xffffffffu, ay, 8);
        az += __shfl_xor_sync(0xffffffffu, az, 8);
        aw += __shfl_xor_sync(0xffffffffu, aw, 8);
        ax += __shfl_xor_sync(0xffffffffu, ax, 16);
        ay += __shfl_xor_sync(0xffffffffu, ay, 16);
        az += __shfl_xor_sync(0xffffffffu, az, 16);
        aw += __shfl_xor_sync(0xffffffffu, aw, 16);
        float inv = 1.f / (S + 1e-16f);
        if (g == 0)
            ((float4*)(g_agg + gw * 128))[h * 8 + l] =
                make_float4(ax * inv, ay * inv, az * inv, aw * inv);
    }
}

// ---------------- whole-matrix mean/var reduction ----------------
__global__ void stats_kernel(const float* __restrict__ a, int n4, float* st) {
    float s = 0.f, q = 0.f;
    const float4* a4 = (const float4*)a;
    for (int i = blockIdx.x * blockDim.x + threadIdx.x; i < n4; i += gridDim.x * blockDim.x) {
        float4 v = a4[i];
        s += v.x + v.y + v.z + v.w;
        q += v.x * v.x + v.y * v.y + v.z * v.z + v.w * v.w;
    }
    #pragma unroll
    for (int o = 16; o > 0; o >>= 1) {
        s += __shfl_xor_sync(0xffffffffu, s, o);
        q += __shfl_xor_sync(0xffffffffu, q, o);
    }
    __shared__ float ss[8], qq[8];
    int w = threadIdx.x >> 5;
    if ((threadIdx.x & 31) == 0) { ss[w] = s; qq[w] = q; }
    __syncthreads();
    if (threadIdx.x == 0) {
        float S = 0.f, Q = 0.f;
        #pragma unroll
        for (int i = 0; i < 8; i++) { S += ss[i]; Q += qq[i]; }
        atomicAdd(st, S);
        atomicAdd(st + 1, Q);
    }
}

// ---------------- launch ----------------
extern "C" void kernel_launch(void* const* d_in, const int* in_sizes, int n_in,
                              void* d_out, int out_size)
{
    const float* x     = (const float*)d_in[0];
    const int*   ei    = (const int*)  d_in[1];
    const float* eattr = (const float*)d_in[2];
    const float* Wl    = (const float*)d_in[3];
    const float* Wr    = (const float*)d_in[4];
    const float* We    = (const float*)d_in[5];
    const float* att   = (const float*)d_in[6];
    const float* lnw   = (const float*)d_in[7];
    const float* lnb   = (const float*)d_in[8];
    const float* Wout  = (const float*)d_in[9];
    const float* bout  = (const float*)d_in[10];
    float* out = (float*)d_out;

    float* xl;  cudaGetSymbolAddress((void**)&xl,  g_xl);
    float* xr;  cudaGetSymbolAddress((void**)&xr,  g_xr);
    float* agg; cudaGetSymbolAddress((void**)&agg, g_agg);
    float* st;  cudaGetSymbolAddress((void**)&st,  g_stats);
    uint32_t* P; cudaGetSymbolAddress((void**)&P,  g_wpack);

    const size_t GSMEM = 2 * 64 * 132 * sizeof(float);  // 67.6 KB
    cudaFuncSetAttribute(gemm_mma<4>, cudaFuncAttributeMaxDynamicSharedMemorySize, (int)GSMEM);
    cudaFuncSetAttribute(gemm_mma<2>, cudaFuncAttributeMaxDynamicSharedMemorySize, (int)GSMEM);

    const float inv_count = 1.f / (float)(NN * HID);
    const int NB_NODE = (NN + 255) / 256;       // 196
    const int GEMM_BLOCKS = (NN + 63) / 64;     // 782
    const int EDGE_BLOCKS = (NN + 7) / 8;       // 6250

    // weight pack (tf32 hi/lo, fragment order)
    pack_kernel<<<3 * 64, 256>>>(Wl,   P,              3);
    pack_kernel<<<3 * 64, 256>>>(Wr,   P + 3 * 16384,  3);
    pack_kernel<<<64,     256>>>(Wout, P + 6 * 16384,  1);

    // CSR build
    zero_kernel<<<NB_NODE, 256>>>();
    hist_kernel<<<(EE + 255) / 256, 256>>>(ei);
    blocksum_kernel<<<NB_NODE, 256>>>();
    bscan_kernel<<<1, 256>>>(NB_NODE);
    offs_kernel<<<NB_NODE, 256>>>();
    scatter_kernel<<<(EE + 255) / 256, 256>>>(ei, eattr);

    for (int l = 0; l < LAY; l++) {
        const float* A = (l == 0) ? x : agg;
        const float* stats = (l == 0) ? nullptr : (st + 2 * (l - 1));
        const float* w = (l == 0) ? nullptr : (lnw + 128 * (l - 1));
        const float* b = (l == 0) ? nullptr : (lnb + 128 * (l - 1));
        gemm_mma<4><<<GEMM_BLOCKS, 256, GSMEM>>>(
            A, P + l * 16384, P + (3 + l) * 16384, xl, xr,
            stats, w, b, nullptr, NN, inv_count);
        edge_kernel<<<EDGE_BLOCKS, 256>>>(We + l * 384, att + l * 128);
        stats_kernel<<<512, 256>>>(agg, NN * HID / 4, st + 2 * l);
    }

    gemm_mma<2><<<GEMM_BLOCKS, 256, GSMEM>>>(
        agg, P + 6 * 16384, nullptr, out, nullptr,
        st + 4, lnw + 256, lnb + 256, bout, NN, inv_count);
}